// round 4
// baseline (speedup 1.0000x reference)
#include <cuda_runtime.h>
#include <cuda_bf16.h>

#define NTHREADS 256
#define MAX_BLOCKS 2048

__device__ float2 g_partials[MAX_BLOCKS];
__device__ unsigned int g_ticket = 0;   // self-resetting via atomicInc wrap

__device__ __forceinline__ float2 ldcg_f2(const float2* p) {
    float2 v;
    asm volatile("ld.global.cg.v2.f32 {%0, %1}, [%2];"
                 : "=f"(v.x), "=f"(v.y) : "l"(p));
    return v;
}

__device__ __forceinline__ void accum_elem(float x, float p, float n, float y,
                                           float& s_bce, float& s_cnt) {
    float m   = (fminf(p, n) > 0.5f) ? 1.0f : 0.0f;
    float t   = __expf(-fabsf(x));                       // FMUL + MUFU.EX2
    float sp  = 0.69314718056f * __log2f(1.0f + t);      // FADD + MUFU.LG2 + FMUL
    float bce = fmaxf(x, 0.0f) - x * y + sp;
    s_bce += bce * m;
    s_cnt += m;
}

__device__ __forceinline__ void accum_vec(float4 xv, float4 pv, float4 nv, float y,
                                          float& s_bce, float& s_cnt) {
    accum_elem(xv.x, pv.x, nv.x, y, s_bce, s_cnt);
    accum_elem(xv.y, pv.y, nv.y, y, s_bce, s_cnt);
    accum_elem(xv.z, pv.z, nv.z, y, s_bce, s_cnt);
    accum_elem(xv.w, pv.w, nv.w, y, s_bce, s_cnt);
}

__global__ __launch_bounds__(NTHREADS) void loss_kernel(
    const float4* __restrict__ x4,
    const float*  __restrict__ label,
    const float4* __restrict__ pm4,
    const float4* __restrict__ nm4,
    float* __restrict__ out,
    int hw4, int nblocks_total)
{
    const int   b    = blockIdx.y;
    const float y    = __ldg(&label[b]);
    const int   base = b * hw4;

    float s_bce = 0.0f;
    float s_cnt = 0.0f;

    const int stride = gridDim.x * blockDim.x;
    int i = blockIdx.x * blockDim.x + threadIdx.x;

    // Unroll x2: 6 independent LDG.128 in flight before any math.
    for (; i + stride < hw4; i += 2 * stride) {
        const int j = i + stride;
        float4 xv0 = __ldcs(&x4 [base + i]);
        float4 pv0 = __ldcs(&pm4[base + i]);
        float4 nv0 = __ldcs(&nm4[base + i]);
        float4 xv1 = __ldcs(&x4 [base + j]);
        float4 pv1 = __ldcs(&pm4[base + j]);
        float4 nv1 = __ldcs(&nm4[base + j]);
        accum_vec(xv0, pv0, nv0, y, s_bce, s_cnt);
        accum_vec(xv1, pv1, nv1, y, s_bce, s_cnt);
    }
    if (i < hw4) {
        float4 xv = __ldcs(&x4 [base + i]);
        float4 pv = __ldcs(&pm4[base + i]);
        float4 nv = __ldcs(&nm4[base + i]);
        accum_vec(xv, pv, nv, y, s_bce, s_cnt);
    }

    // Warp reduction
    #pragma unroll
    for (int off = 16; off > 0; off >>= 1) {
        s_bce += __shfl_down_sync(0xFFFFFFFFu, s_bce, off);
        s_cnt += __shfl_down_sync(0xFFFFFFFFu, s_cnt, off);
    }

    // Block reduction
    __shared__ float sh_bce[8];
    __shared__ float sh_cnt[8];
    const int wid = threadIdx.x >> 5;
    const int lid = threadIdx.x & 31;
    if (lid == 0) { sh_bce[wid] = s_bce; sh_cnt[wid] = s_cnt; }
    __syncthreads();

    __shared__ bool is_last;
    const int blin = blockIdx.y * gridDim.x + blockIdx.x;
    if (threadIdx.x < 32) {
        float bsum = (lid < (NTHREADS >> 5)) ? sh_bce[lid] : 0.0f;
        float csum = (lid < (NTHREADS >> 5)) ? sh_cnt[lid] : 0.0f;
        #pragma unroll
        for (int off = 4; off > 0; off >>= 1) {
            bsum += __shfl_down_sync(0xFFFFFFFFu, bsum, off);
            csum += __shfl_down_sync(0xFFFFFFFFu, csum, off);
        }
        if (lid == 0) {
            g_partials[blin] = make_float2(bsum, csum);
            __threadfence();
            unsigned t = atomicInc(&g_ticket, (unsigned)nblocks_total - 1);
            is_last = (t == (unsigned)nblocks_total - 1);
        }
    }
    __syncthreads();

    if (is_last) {
        double db = 0.0, dc = 0.0;
        for (int k = threadIdx.x; k < nblocks_total; k += blockDim.x) {
            float2 p = ldcg_f2(&g_partials[k]);
            db += (double)p.x;
            dc += (double)p.y;
        }
        #pragma unroll
        for (int off = 16; off > 0; off >>= 1) {
            db += __shfl_down_sync(0xFFFFFFFFu, db, off);
            dc += __shfl_down_sync(0xFFFFFFFFu, dc, off);
        }
        __shared__ double dh_b[8];
        __shared__ double dh_c[8];
        if (lid == 0) { dh_b[wid] = db; dh_c[wid] = dc; }
        __syncthreads();
        if (threadIdx.x < 32) {
            double b2 = (lid < (NTHREADS >> 5)) ? dh_b[lid] : 0.0;
            double c2 = (lid < (NTHREADS >> 5)) ? dh_c[lid] : 0.0;
            #pragma unroll
            for (int off = 4; off > 0; off >>= 1) {
                b2 += __shfl_down_sync(0xFFFFFFFFu, b2, off);
                c2 += __shfl_down_sync(0xFFFFFFFFu, c2, off);
            }
            if (lid == 0) {
                if (c2 < 1.0) c2 = 1.0;
                out[0] = (float)(b2 / c2);
            }
        }
    }
}

extern "C" void kernel_launch(void* const* d_in, const int* in_sizes, int n_in,
                              void* d_out, int out_size) {
    const float* x  = (const float*)d_in[0];  // cancer_logits (B,1,H,W)
    const float* y  = (const float*)d_in[1];  // label (B,)
    const float* pm = (const float*)d_in[2];  // prostate_mask
    const float* nm = (const float*)d_in[3];  // needle_mask

    int n   = in_sizes[0];   // B*H*W
    int nb  = in_sizes[1];   // B
    int hw4 = (n / nb) / 4;  // float4s per image

    int bpb = (8 * 148 + nb - 1) / nb;            // ~8 blocks/SM overall
    if (bpb * nb > MAX_BLOCKS) bpb = MAX_BLOCKS / nb;
    int nblocks_total = bpb * nb;

    dim3 grid(bpb, nb, 1);
    loss_kernel<<<grid, NTHREADS>>>(
        (const float4*)x, y, (const float4*)pm, (const float4*)nm,
        (float*)d_out, hw4, nblocks_total);
}

// round 5
// speedup vs baseline: 1.0350x; 1.0350x over previous
#include <cuda_runtime.h>
#include <cuda_bf16.h>

#define NTHREADS 256
#define MAX_BLOCKS 2048

__device__ float2 g_partials[MAX_BLOCKS];
__device__ unsigned int g_ticket = 0;   // self-resetting via atomicInc wrap

__device__ __forceinline__ float2 ldcg_f2(const float2* p) {
    float2 v;
    asm volatile("ld.global.cg.v2.f32 {%0, %1}, [%2];"
                 : "=f"(v.x), "=f"(v.y) : "l"(p));
    return v;
}

__device__ __forceinline__ void accum_elem(float x, float p, float n, float y,
                                           float& s_bce, float& s_cnt) {
    float m   = (fminf(p, n) > 0.5f) ? 1.0f : 0.0f;
    float t   = __expf(-fabsf(x));                       // FMUL + MUFU.EX2
    float sp  = 0.69314718056f * __log2f(1.0f + t);      // FADD + MUFU.LG2 + FMUL
    float bce = fmaxf(x, 0.0f) - x * y + sp;
    s_bce += bce * m;
    s_cnt += m;
}

__device__ __forceinline__ void accum_vec(float4 xv, float4 pv, float4 nv, float y,
                                          float& s_bce, float& s_cnt) {
    accum_elem(xv.x, pv.x, nv.x, y, s_bce, s_cnt);
    accum_elem(xv.y, pv.y, nv.y, y, s_bce, s_cnt);
    accum_elem(xv.z, pv.z, nv.z, y, s_bce, s_cnt);
    accum_elem(xv.w, pv.w, nv.w, y, s_bce, s_cnt);
}

__global__ __launch_bounds__(NTHREADS) void loss_kernel(
    const float4* __restrict__ x4,
    const float*  __restrict__ label,
    const float4* __restrict__ pm4,
    const float4* __restrict__ nm4,
    float* __restrict__ out,
    int hw4, int iters, int nblocks_total)
{
    const int   b    = blockIdx.y;
    const float y    = __ldg(&label[b]);
    const int   base = b * hw4;

    float s_bce = 0.0f;
    float s_cnt = 0.0f;

    const int stride = gridDim.x * blockDim.x;
    int i = blockIdx.x * blockDim.x + threadIdx.x;

    // Counted main loop: no per-iteration bound check; uniform work per thread.
    #pragma unroll 2
    for (int it = 0; it < iters; ++it, i += stride) {
        float4 xv = __ldcs(&x4 [base + i]);
        float4 pv = __ldcs(&pm4[base + i]);
        float4 nv = __ldcs(&nm4[base + i]);
        accum_vec(xv, pv, nv, y, s_bce, s_cnt);
    }
    // Tail (runs only when hw4 % (gridDim.x*blockDim.x) != 0)
    for (; i < hw4; i += stride) {
        float4 xv = __ldcs(&x4 [base + i]);
        float4 pv = __ldcs(&pm4[base + i]);
        float4 nv = __ldcs(&nm4[base + i]);
        accum_vec(xv, pv, nv, y, s_bce, s_cnt);
    }

    // Warp reduction
    #pragma unroll
    for (int off = 16; off > 0; off >>= 1) {
        s_bce += __shfl_down_sync(0xFFFFFFFFu, s_bce, off);
        s_cnt += __shfl_down_sync(0xFFFFFFFFu, s_cnt, off);
    }

    // Block reduction
    __shared__ float sh_bce[8];
    __shared__ float sh_cnt[8];
    const int wid = threadIdx.x >> 5;
    const int lid = threadIdx.x & 31;
    if (lid == 0) { sh_bce[wid] = s_bce; sh_cnt[wid] = s_cnt; }
    __syncthreads();

    __shared__ bool is_last;
    const int blin = blockIdx.y * gridDim.x + blockIdx.x;
    if (threadIdx.x < 32) {
        float bsum = (lid < (NTHREADS >> 5)) ? sh_bce[lid] : 0.0f;
        float csum = (lid < (NTHREADS >> 5)) ? sh_cnt[lid] : 0.0f;
        #pragma unroll
        for (int off = 4; off > 0; off >>= 1) {
            bsum += __shfl_down_sync(0xFFFFFFFFu, bsum, off);
            csum += __shfl_down_sync(0xFFFFFFFFu, csum, off);
        }
        if (lid == 0) {
            g_partials[blin] = make_float2(bsum, csum);
            __threadfence();
            unsigned t = atomicInc(&g_ticket, (unsigned)nblocks_total - 1);
            is_last = (t == (unsigned)nblocks_total - 1);
        }
    }
    __syncthreads();

    if (is_last) {
        double db = 0.0, dc = 0.0;
        for (int k = threadIdx.x; k < nblocks_total; k += blockDim.x) {
            float2 p = ldcg_f2(&g_partials[k]);
            db += (double)p.x;
            dc += (double)p.y;
        }
        #pragma unroll
        for (int off = 16; off > 0; off >>= 1) {
            db += __shfl_down_sync(0xFFFFFFFFu, db, off);
            dc += __shfl_down_sync(0xFFFFFFFFu, dc, off);
        }
        __shared__ double dh_b[8];
        __shared__ double dh_c[8];
        if (lid == 0) { dh_b[wid] = db; dh_c[wid] = dc; }
        __syncthreads();
        if (threadIdx.x < 32) {
            double b2 = (lid < (NTHREADS >> 5)) ? dh_b[lid] : 0.0;
            double c2 = (lid < (NTHREADS >> 5)) ? dh_c[lid] : 0.0;
            #pragma unroll
            for (int off = 4; off > 0; off >>= 1) {
                b2 += __shfl_down_sync(0xFFFFFFFFu, b2, off);
                c2 += __shfl_down_sync(0xFFFFFFFFu, c2, off);
            }
            if (lid == 0) {
                if (c2 < 1.0) c2 = 1.0;
                out[0] = (float)(b2 / c2);
            }
        }
    }
}

extern "C" void kernel_launch(void* const* d_in, const int* in_sizes, int n_in,
                              void* d_out, int out_size) {
    const float* x  = (const float*)d_in[0];  // cancer_logits (B,1,H,W)
    const float* y  = (const float*)d_in[1];  // label (B,)
    const float* pm = (const float*)d_in[2];  // prostate_mask
    const float* nm = (const float*)d_in[3];  // needle_mask

    int n   = in_sizes[0];   // B*H*W
    int nb  = in_sizes[1];   // B
    int hw4 = (n / nb) / 4;  // float4s per image

    // Pick blocks-per-image so the grid is a single wave and work divides evenly:
    // bpb=32, B=32 -> 1024 blocks (6.9/SM), 8192 threads/image, exactly
    // hw4/8192 = 8 full iterations per thread for 512x512 images.
    int bpb = 32;
    while (bpb * nb > MAX_BLOCKS && bpb > 1) bpb >>= 1;
    int nblocks_total = bpb * nb;
    int tpi   = bpb * NTHREADS;      // threads per image
    int iters = hw4 / tpi;           // uniform counted iterations (tail loop covers rest)

    dim3 grid(bpb, nb, 1);
    loss_kernel<<<grid, NTHREADS>>>(
        (const float4*)x, y, (const float4*)pm, (const float4*)nm,
        (float*)d_out, hw4, iters, nblocks_total);
}

// round 7
// speedup vs baseline: 1.1233x; 1.0854x over previous
#include <cuda_runtime.h>
#include <cuda_bf16.h>

#define NTHREADS 256
#define MAX_BLOCKS 2048

__device__ float2 g_partials[MAX_BLOCKS];
__device__ unsigned int g_ticket = 0;   // self-resetting via atomicInc wrap

__device__ __forceinline__ float2 ldcg_f2(const float2* p) {
    float2 v;
    asm volatile("ld.global.cg.v2.f32 {%0, %1}, [%2];"
                 : "=f"(v.x), "=f"(v.y) : "l"(p));
    return v;
}

struct f8 { float v[8]; };

// 256-bit read-only load with L2 evict_last (v8.b32 is the only legal form on
// sm_103a ptxas). Working set (100.7MB) fits L2 (126MB): keep it resident
// across graph replays.
__device__ __forceinline__ f8 ldg_el8(const float* p) {
    f8 r;
    asm("ld.global.nc.L2::evict_last.v8.b32 {%0,%1,%2,%3,%4,%5,%6,%7}, [%8];"
        : "=f"(r.v[0]), "=f"(r.v[1]), "=f"(r.v[2]), "=f"(r.v[3]),
          "=f"(r.v[4]), "=f"(r.v[5]), "=f"(r.v[6]), "=f"(r.v[7])
        : "l"(p));
    return r;
}

__device__ __forceinline__ void accum_elem(float x, float p, float n, float y,
                                           float& s_bce, float& s_cnt) {
    float m   = (fminf(p, n) > 0.5f) ? 1.0f : 0.0f;
    float t   = __expf(-fabsf(x));                       // FMUL + MUFU.EX2
    float sp  = 0.69314718056f * __log2f(1.0f + t);      // FADD + MUFU.LG2 + FMUL
    float bce = fmaxf(x, 0.0f) - x * y + sp;
    s_bce += bce * m;
    s_cnt += m;
}

__global__ __launch_bounds__(NTHREADS) void loss_kernel(
    const float* __restrict__ x,
    const float* __restrict__ label,
    const float* __restrict__ pm,
    const float* __restrict__ nm,
    float* __restrict__ out,
    int hw8, int nblocks_total)
{
    const int   b    = blockIdx.y;
    const float y    = __ldg(&label[b]);
    const long long base = (long long)b * hw8 * 8;   // float offset of this image

    float s_bce = 0.0f;
    float s_cnt = 0.0f;

    const int stride = gridDim.x * blockDim.x;
    for (int i = blockIdx.x * blockDim.x + threadIdx.x; i < hw8; i += stride) {
        const long long off = base + (long long)i * 8;
        f8 xv = ldg_el8(x  + off);
        f8 pv = ldg_el8(pm + off);
        f8 nv = ldg_el8(nm + off);
        #pragma unroll
        for (int k = 0; k < 8; ++k)
            accum_elem(xv.v[k], pv.v[k], nv.v[k], y, s_bce, s_cnt);
    }

    // Warp reduction
    #pragma unroll
    for (int off = 16; off > 0; off >>= 1) {
        s_bce += __shfl_down_sync(0xFFFFFFFFu, s_bce, off);
        s_cnt += __shfl_down_sync(0xFFFFFFFFu, s_cnt, off);
    }

    // Block reduction
    __shared__ float sh_bce[8];
    __shared__ float sh_cnt[8];
    const int wid = threadIdx.x >> 5;
    const int lid = threadIdx.x & 31;
    if (lid == 0) { sh_bce[wid] = s_bce; sh_cnt[wid] = s_cnt; }
    __syncthreads();

    __shared__ bool is_last;
    const int blin = blockIdx.y * gridDim.x + blockIdx.x;
    if (threadIdx.x < 32) {
        float bsum = (lid < (NTHREADS >> 5)) ? sh_bce[lid] : 0.0f;
        float csum = (lid < (NTHREADS >> 5)) ? sh_cnt[lid] : 0.0f;
        #pragma unroll
        for (int off = 4; off > 0; off >>= 1) {
            bsum += __shfl_down_sync(0xFFFFFFFFu, bsum, off);
            csum += __shfl_down_sync(0xFFFFFFFFu, csum, off);
        }
        if (lid == 0) {
            g_partials[blin] = make_float2(bsum, csum);
            __threadfence();
            unsigned t = atomicInc(&g_ticket, (unsigned)nblocks_total - 1);
            is_last = (t == (unsigned)nblocks_total - 1);
        }
    }
    __syncthreads();

    if (is_last) {
        double db = 0.0, dc = 0.0;
        for (int k = threadIdx.x; k < nblocks_total; k += blockDim.x) {
            float2 p = ldcg_f2(&g_partials[k]);
            db += (double)p.x;
            dc += (double)p.y;
        }
        #pragma unroll
        for (int off = 16; off > 0; off >>= 1) {
            db += __shfl_down_sync(0xFFFFFFFFu, db, off);
            dc += __shfl_down_sync(0xFFFFFFFFu, dc, off);
        }
        __shared__ double dh_b[8];
        __shared__ double dh_c[8];
        if (lid == 0) { dh_b[wid] = db; dh_c[wid] = dc; }
        __syncthreads();
        if (threadIdx.x < 32) {
            double b2 = (lid < (NTHREADS >> 5)) ? dh_b[lid] : 0.0;
            double c2 = (lid < (NTHREADS >> 5)) ? dh_c[lid] : 0.0;
            #pragma unroll
            for (int off = 4; off > 0; off >>= 1) {
                b2 += __shfl_down_sync(0xFFFFFFFFu, b2, off);
                c2 += __shfl_down_sync(0xFFFFFFFFu, c2, off);
            }
            if (lid == 0) {
                if (c2 < 1.0) c2 = 1.0;
                out[0] = (float)(b2 / c2);
            }
        }
    }
}

extern "C" void kernel_launch(void* const* d_in, const int* in_sizes, int n_in,
                              void* d_out, int out_size) {
    const float* x  = (const float*)d_in[0];  // cancer_logits (B,1,H,W)
    const float* y  = (const float*)d_in[1];  // label (B,)
    const float* pm = (const float*)d_in[2];  // prostate_mask
    const float* nm = (const float*)d_in[3];  // needle_mask

    int n   = in_sizes[0];   // B*H*W
    int nb  = in_sizes[1];   // B
    int hw8 = (n / nb) / 8;  // float8s per image (H*W=262144 -> 32768)

    // ~40 regs with v8 loads -> 6 blocks/SM max. Keep the grid a SINGLE wave:
    // bpb * nb <= 6 * 148 = 888.  For nb=32: bpb=27 -> 864 blocks.
    int bpb = (6 * 148) / nb;
    if (bpb < 1) bpb = 1;
    while (bpb * nb > MAX_BLOCKS && bpb > 1) bpb--;
    int nblocks_total = bpb * nb;

    dim3 grid(bpb, nb, 1);
    loss_kernel<<<grid, NTHREADS>>>(
        x, y, pm, nm, (float*)d_out, hw8, nblocks_total);
}